// round 10
// baseline (speedup 1.0000x reference)
#include <cuda_runtime.h>
#include <cstdint>

#define N_FRAMES    16384
#define NUM_BIN     257
#define NUM_CH      8
#define PLANE_F     (NUM_BIN * NUM_CH)        // 2056 floats
#define PLANE_B     (PLANE_F * 4)             // 8224 bytes
#define FRAME_B     (2 * PLANE_B)             // 16448 bytes, contiguous per frame
#define FPB         2                         // frames per block
#define TILE_B      (FPB * FRAME_B)           // 32896 bytes
#define ITEMS       (FPB * NUM_BIN * 2)       // 1028 half-bin work items / block

__global__ __launch_bounds__(256) void beamform_kernel(
    const float* __restrict__ x,    // [16384, 2, 257, 8]
    const float* __restrict__ W,    // [24, 2, 257, 8]
    const int* __restrict__ beam,   // [16384] (int32 payload)
    float* __restrict__ out)        // [16384, 2, 257, 1]
{
    __shared__ __align__(128) char sx[TILE_B];
    __shared__ __align__(8) unsigned long long mbar;

    unsigned tid = threadIdx.x;
    unsigned f0  = blockIdx.x * FPB;

    uint32_t mbar_a = (uint32_t)__cvta_generic_to_shared(&mbar);
    uint32_t sx_a   = (uint32_t)__cvta_generic_to_shared(sx);

    if (tid == 0) {
        asm volatile("mbarrier.init.shared.b64 [%0], 1;" :: "r"(mbar_a) : "memory");
    }
    __syncthreads();

    if (tid == 0) {
        asm volatile("mbarrier.arrive.expect_tx.shared.b64 _, [%0], %1;"
                     :: "r"(mbar_a), "r"((uint32_t)TILE_B) : "memory");
        const char* gsrc = (const char*)x + (size_t)f0 * FRAME_B;
        asm volatile("cp.async.bulk.shared::cta.global.mbarrier::complete_tx::bytes "
                     "[%0], [%1], %2, [%3];"
                     :: "r"(sx_a), "l"(gsrc), "r"((uint32_t)TILE_B), "r"(mbar_a)
                     : "memory");
    }

    // wait phase 0 (all threads; only thread 0 arrived, tx completes the phase)
    {
        uint32_t done;
        asm volatile(
            "{\n\t.reg .pred p;\n\t"
            "mbarrier.try_wait.parity.shared.b64 p, [%1], 0;\n\t"
            "selp.b32 %0, 1, 0, p;\n\t}"
            : "=r"(done) : "r"(mbar_a) : "memory");
        while (!done) {
            asm volatile(
                "{\n\t.reg .pred p;\n\t"
                "mbarrier.try_wait.parity.shared.b64 p, [%1], 0;\n\t"
                "selp.b32 %0, 1, 0, p;\n\t}"
                : "=r"(done) : "r"(mbar_a) : "memory");
        }
    }

    int b0 = __ldg(beam + f0);
    int b1 = __ldg(beam + f0 + 1);

    // 4 full passes of 256 items + a 4-item tail
    #pragma unroll
    for (int i = 0; i < 4; i++) {
        unsigned it   = tid + 256u * i;          // < 1024
        unsigned fl   = it >= (unsigned)(NUM_BIN * 2);   // 514 items per frame
        unsigned rem  = it - fl * (NUM_BIN * 2);
        unsigned bin  = rem >> 1;
        unsigned half = rem & 1u;

        const float4* xr = (const float4*)(sx + fl * FRAME_B + bin * 32 + half * 16);
        const float4* xi = (const float4*)((const char*)xr + PLANE_B);
        float4 vxr = *xr, vxi = *xi;

        int b = fl ? b1 : b0;
        size_t wb = (size_t)b * 2 * PLANE_F + (size_t)bin * NUM_CH + half * 4;
        float4 wr = __ldg((const float4*)(W + wb));
        float4 wi = __ldg((const float4*)(W + wb + PLANE_F));

        float pr = vxr.x * wr.x + vxr.y * wr.y + vxr.z * wr.z + vxr.w * wr.w
                 + vxi.x * wi.x + vxi.y * wi.y + vxi.z * wi.z + vxi.w * wi.w;
        float pi = vxi.x * wr.x + vxi.y * wr.y + vxi.z * wr.z + vxi.w * wr.w
                 - (vxr.x * wi.x + vxr.y * wi.y + vxr.z * wi.z + vxr.w * wi.w);

        pr += __shfl_xor_sync(0xffffffffu, pr, 1);
        pi += __shfl_xor_sync(0xffffffffu, pi, 1);

        size_t o = (size_t)(f0 + fl) * (2 * NUM_BIN) + half * NUM_BIN + bin;
        __stcs(out + o, half ? pi : pr);
    }

    // tail: items 1024..1027 (frame 1, bins 255,256 x both halves) — lanes 0-3 of warp 0
    if (tid < 4) {
        unsigned it   = 1024u + tid;
        unsigned rem  = it - (unsigned)(NUM_BIN * 2);    // frame 1
        unsigned bin  = rem >> 1;
        unsigned half = rem & 1u;

        const float4* xr = (const float4*)(sx + FRAME_B + bin * 32 + half * 16);
        const float4* xi = (const float4*)((const char*)xr + PLANE_B);
        float4 vxr = *xr, vxi = *xi;

        size_t wb = (size_t)b1 * 2 * PLANE_F + (size_t)bin * NUM_CH + half * 4;
        float4 wr = __ldg((const float4*)(W + wb));
        float4 wi = __ldg((const float4*)(W + wb + PLANE_F));

        float pr = vxr.x * wr.x + vxr.y * wr.y + vxr.z * wr.z + vxr.w * wr.w
                 + vxi.x * wi.x + vxi.y * wi.y + vxi.z * wi.z + vxi.w * wi.w;
        float pi = vxi.x * wr.x + vxi.y * wr.y + vxi.z * wr.z + vxi.w * wr.w
                 - (vxr.x * wi.x + vxr.y * wi.y + vxr.z * wi.z + vxr.w * wi.w);

        pr += __shfl_xor_sync(0x0000000Fu, pr, 1);
        pi += __shfl_xor_sync(0x0000000Fu, pi, 1);

        size_t o = (size_t)(f0 + 1) * (2 * NUM_BIN) + half * NUM_BIN + bin;
        __stcs(out + o, half ? pi : pr);
    }
}

extern "C" void kernel_launch(void* const* d_in, const int* in_sizes, int n_in,
                              void* d_out, int out_size) {
    const float* x    = (const float*)d_in[0];
    const float* W    = (const float*)d_in[1];
    const int*   beam = (const int*)d_in[2];
    float*       out  = (float*)d_out;

    // maximize smem carveout so ~6 blocks (33KB each) fit per SM
    cudaFuncSetAttribute(beamform_kernel,
                         cudaFuncAttributePreferredSharedMemoryCarveout,
                         cudaSharedmemCarveoutMaxShared);

    unsigned blocks = N_FRAMES / FPB;   // 8192
    beamform_kernel<<<blocks, 256>>>(x, W, beam, out);
}